// round 9
// baseline (speedup 1.0000x reference)
#include <cuda_runtime.h>
#include <math.h>

// ---------------- problem constants ----------------
namespace {
constexpr int kN   = 50625;          // SIDE^4
constexpr int kB   = 16;             // batch
constexpr int kBot = 26;
constexpr int kL   = 6;
constexpr int kTPB = 256;
constexpr int kTokB = 512;           // tokens per block (2 per thread)
constexpr int kBPB = 99;             // 99*512 = 50688 padded tokens
constexpr int kNP  = kBPB * kTokB;
constexpr int kGrid = kB * kBPB;     // 1584
constexpr float kScale = 0.5f;       // DH^-0.5
}

typedef unsigned long long u64;

// ---------------- parameter banks ----------------
struct alignas(16) CParams {
  float Wqkv[1536];                  // (16,96) natural [d][96]
  float WqWo[256];                   // folded Wq@Wo [d][16]
  float WrWo[256];                   // folded Wr@Wo [(h*2+p)][16]
  float W1[1024];                    // (16,64) natural [d][64]
  float W2[1024];                    // (64,16) natural [j][16]
  float ln1g[16], ln1b[16], ln2g[16], ln2b[16];
  float wk[2], pad0[2];
  float boP[16];                     // folded b_o + (b_r rows)@Wo
  float B1[64], B2[16];
  float nLn1g[16], nLn1b[16];
  float nWqlog[4], pad1[4];
  float nWq[512];                    // [d][32] q columns of layer i+1
};
struct alignas(16) CA0 {
  float ln1g[16], ln1b[16], wq[4], pad[4];
  float Wq[512];                     // [d][32]
};
struct alignas(16) CGlob {
  float Wemb[kBot * 16];
  float bemb[16], Wout[16], bout[4], pad[4];
};

__constant__ CParams cP;
__constant__ CA0 cA;
__constant__ CGlob cG;

// ---------------- scratch ----------------
// x blocked-SoA: [b][blk][m(0..3)][slot(0..511)] as float4
__device__ float g_x[(size_t)kB * kBPB * 4 * kTokB * 4];
__device__ float4 g_rot[kNP];
__device__ float g_partQ[kGrid * 40];
__device__ float g_partK[kGrid * 40];
__device__ CParams g_banks[kL];
__device__ CA0 g_a0s;
__device__ CGlob g_gls;

// ---------------- packed f32x2 helpers ----------------
__device__ __forceinline__ u64 pack2(float lo, float hi) {
  u64 r; asm("mov.b64 %0,{%1,%2};" : "=l"(r) : "f"(lo), "f"(hi)); return r;
}
__device__ __forceinline__ void unpack2(u64 v, float& lo, float& hi) {
  asm("mov.b64 {%0,%1},%2;" : "=f"(lo), "=f"(hi) : "l"(v));
}
__device__ __forceinline__ u64 fma2(u64 a, u64 b, u64 c) {
  u64 d; asm("fma.rn.f32x2 %0,%1,%2,%3;" : "=l"(d) : "l"(a), "l"(b), "l"(c)); return d;
}
__device__ __forceinline__ void ldc4(const float* p, u64& lo, u64& hi) {
  ulonglong2 v = *reinterpret_cast<const ulonglong2*>(p);
  lo = v.x; hi = v.y;
}

// ---------------- scalar helpers ----------------
__device__ __forceinline__ void ln16(const float* x, const float* g,
                                     const float* bb, float* y) {
  float m = 0.f;
#pragma unroll
  for (int d = 0; d < 16; d++) m += x[d];
  m *= (1.f / 16.f);
  float v = 0.f;
#pragma unroll
  for (int d = 0; d < 16; d++) { float t = x[d] - m; v = fmaf(t, t, v); }
  v *= (1.f / 16.f);
  float r = rsqrtf(v + 1e-5f);
#pragma unroll
  for (int d = 0; d < 16; d++) y[d] = (x[d] - m) * r * g[d] + bb[d];
}

__device__ __forceinline__ void rot_cs(int n, float& c0, float& s0,
                                       float& c1, float& s1) {
  float nf = (float)n;
  float p0 = nf * 3.14159265358979323846f;
  float p1 = nf * 15.70796326794896619231f;
  double d0 = (double)p0 - (double)n * 3.14159265358979323846;
  double d1 = (double)p1 - (double)n * 15.70796326794896619231;
  float e0 = (float)d0, e1 = (float)d1;
  float sgn = (n & 1) ? -1.f : 1.f;
  c0 = sgn * (1.f - 0.5f * e0 * e0);
  s0 = sgn * e0 * (1.f - 0.1666666667f * e0 * e0);
  c1 = sgn * (1.f - 0.5f * e1 * e1);
  s1 = sgn * e1 * (1.f - 0.1666666667f * e1 * e1);
}

__device__ __forceinline__ float gelu_fast(float p) {
  float xs = p * 0.7071067811865475f;
  float ax = fabsf(xs);
  float t = __fdividef(1.f, fmaf(0.3275911f, ax, 1.f));
  float poly = t * fmaf(t, fmaf(t, fmaf(t, fmaf(t, 1.061405429f,
                   -1.453152027f), 1.421413741f), -0.284496736f),
                   0.254829592f);
  float e = __expf(-ax * ax);
  float er = 1.f - poly * e;
  er = copysignf(er, xs);
  return 0.5f * p * (1.f + er);
}

// block reduction of 40 per-thread floats via smem transpose (paired 64-bit)
__device__ __forceinline__ void reduce40_pairs(const float* vals, float* partOut) {
  __shared__ u64 sT[20 * 257];
  __shared__ float sS[40][12];
  int t = threadIdx.x;
#pragma unroll
  for (int p = 0; p < 20; p++)
    sT[p * 257 + t] = pack2(vals[2*p], vals[2*p+1]);
  __syncthreads();
  if (t < 240) {
    int p = t / 12, sl = t % 12;
    float s0 = 0.f, s1 = 0.f;
    const u64* row = &sT[p * 257];
#pragma unroll
    for (int i = sl; i < kTPB; i += 12) {
      float a, b; unpack2(row[i], a, b);
      s0 += a; s1 += b;
    }
    sS[2*p][sl] = s0; sS[2*p+1][sl] = s1;
  }
  __syncthreads();
  if (t < 40) {
    float s = 0.f;
#pragma unroll
    for (int j = 0; j < 12; j++) s += sS[t][j];
    partOut[t] = s;
  }
}

// inline finalize: per-batch partials -> 32 global weights in smem.
__device__ __forceinline__ void finalize_inline(const float* part, int b,
                                                float* sg32) {
  __shared__ float sf[40][6];
  int t = threadIdx.x;
  const float* pp = part + (size_t)b * kBPB * 40;
  if (t < 240) {
    int k = t / 6, sl = t % 6;
    float acc = 0.f;
    for (int blk = sl; blk < kBPB; blk += 6) acc += pp[blk*40 + k];
    sf[k][sl] = acc;
  }
  __syncthreads();
  if (t < 32) {
    int h = t >> 2, d = t & 3;
    float den = sf[h*5][0]+sf[h*5][1]+sf[h*5][2]+sf[h*5][3]+sf[h*5][4]+sf[h*5][5];
    int r = h*5 + 1 + d;
    float num = sf[r][0]+sf[r][1]+sf[r][2]+sf[r][3]+sf[r][4]+sf[r][5];
    sg32[t] = num / den;
  }
  __syncthreads();
}

__device__ __forceinline__ float4* xblock(int b, int blk) {
  return reinterpret_cast<float4*>(g_x) + ((size_t)(b * kBPB + blk) * 4) * kTokB;
}

// stage-A stats for a token pair: LN1 -> q -> rotary + q-logit partials.
__device__ __forceinline__ void qstats_reduce2(
    const float x0[16], const float x1[16], bool a0f, bool a1f, int n0, int n1,
    const float* lg, const float* lb, const float* Wq, const float* wql,
    float* partOut) {
  float y0[16], y1[16];
  ln16(x0, lg, lb, y0);
  ln16(x1, lg, lb, y1);
  float4 r0 = g_rot[n0], r1 = g_rot[n1];
  float vals[40];
#pragma unroll
  for (int hp = 0; hp < 2; hp++) {
    u64 a0[8], a1[8];
#pragma unroll
    for (int m = 0; m < 8; m++) { a0[m] = 0ull; a1[m] = 0ull; }
#pragma unroll
    for (int d = 0; d < 16; d++) {
      u64 yd0 = pack2(y0[d], y0[d]);
      u64 yd1 = pack2(y1[d], y1[d]);
      const float* row = &Wq[d * 32 + hp * 16];
#pragma unroll
      for (int h2 = 0; h2 < 4; h2++) {
        u64 w0, w1; ldc4(row + 4 * h2, w0, w1);
        a0[2*h2]   = fma2(w0, yd0, a0[2*h2]);
        a0[2*h2+1] = fma2(w1, yd0, a0[2*h2+1]);
        a1[2*h2]   = fma2(w0, yd1, a1[2*h2]);
        a1[2*h2+1] = fma2(w1, yd1, a1[2*h2+1]);
      }
    }
#pragma unroll
    for (int h2 = 0; h2 < 4; h2++) {
      int h = hp * 4 + h2;
      float q0, q1, q2, q3, p0, p1, p2, p3;
      unpack2(a0[2*h2], q0, q1); unpack2(a0[2*h2+1], q2, q3);
      unpack2(a1[2*h2], p0, p1); unpack2(a1[2*h2+1], p2, p3);
      float lg0 = (q0*wql[0] + q1*wql[1] + q2*wql[2] + q3*wql[3]) * kScale;
      float lg1 = (p0*wql[0] + p1*wql[1] + p2*wql[2] + p3*wql[3]) * kScale;
      float e0 = a0f ? __expf(lg0) : 0.f;
      float e1 = a1f ? __expf(lg1) : 0.f;
      vals[h*5+0] = e0 + e1;
      vals[h*5+1] = e0*(q0*r0.x - q1*r0.y) + e1*(p0*r1.x - p1*r1.y);
      vals[h*5+2] = e0*(q1*r0.x + q0*r0.y) + e1*(p1*r1.x + p0*r1.y);
      vals[h*5+3] = e0*(q2*r0.z - q3*r0.w) + e1*(p2*r1.z - p3*r1.w);
      vals[h*5+4] = e0*(q3*r0.z + q2*r0.w) + e1*(p3*r1.z + p2*r1.w);
    }
  }
  reduce40_pairs(vals, partOut);
}

// ---------------- prep kernels ----------------
__global__ void rotprep_kernel() {
  int n = blockIdx.x * kTPB + threadIdx.x;
  if (n >= kNP) return;
  float c0, s0, c1, s1; rot_cs(n, c0, s0, c1, s1);
  g_rot[n] = make_float4(c0, s0, c1, s1);
}

__global__ void gather_kernel(
    const float* __restrict__ Wqkv, const float* __restrict__ ln1g,
    const float* __restrict__ ln1b, const float* __restrict__ wq,
    const float* __restrict__ wk, const float* __restrict__ Wr,
    const float* __restrict__ br, const float* __restrict__ Wo,
    const float* __restrict__ bo, const float* __restrict__ ln2g,
    const float* __restrict__ ln2b, const float* __restrict__ W1,
    const float* __restrict__ b1, const float* __restrict__ W2,
    const float* __restrict__ b2, const float* __restrict__ Wemb,
    const float* __restrict__ bemb, const float* __restrict__ Wout,
    const float* __restrict__ bout) {
  int i = blockIdx.x;
  int t = threadIdx.x;
  if (i < kL) {
    CParams* s = &g_banks[i];
    for (int k = t; k < 1536; k += kTPB) s->Wqkv[k] = Wqkv[i*1536 + k];
    for (int k = t; k < 1024; k += kTPB) s->W1[k]  = W1[i*1024 + k];
    for (int k = t; k < 1024; k += kTPB) s->W2[k]  = W2[i*1024 + k];
    {
      int d = t >> 4, e = t & 15;
      float acc = 0.f;
      for (int c = 0; c < 32; c++)
        acc += Wqkv[i*1536 + d*96 + c] * Wo[i*512 + c*16 + e];
      s->WqWo[t] = acc;
    }
    {
      int h = t >> 5, p = (t >> 4) & 1, e = t & 15;
      float acc = 0.f;
      for (int j = 0; j < 4; j++)
        acc += Wr[i*8 + p*4 + j] * Wo[i*512 + (4*h + j)*16 + e];
      s->WrWo[t] = acc;
    }
    if (t < 16) {
      float acc = bo[i*16 + t];
      for (int h = 0; h < 8; h++)
        for (int j = 0; j < 4; j++)
          acc += br[i*4 + j] * Wo[i*512 + (4*h + j)*16 + t];
      s->boP[t] = acc;
    }
    int jn = (i + 1 < kL) ? i + 1 : i;
    for (int k = t; k < 512; k += kTPB) {
      int d = k >> 5, c = k & 31;
      s->nWq[k] = Wqkv[jn*1536 + d*96 + c];
    }
    if (t < 16) {
      s->ln1g[t] = ln1g[i*16+t]; s->ln1b[t] = ln1b[i*16+t];
      s->ln2g[t] = ln2g[i*16+t]; s->ln2b[t] = ln2b[i*16+t];
      s->B2[t] = b2[i*16+t];
      s->nLn1g[t] = ln1g[jn*16+t]; s->nLn1b[t] = ln1b[jn*16+t];
    }
    if (t < 64) s->B1[t] = b1[i*64+t];
    if (t < 4)  s->nWqlog[t] = wq[jn*4+t];
    if (t < 2)  s->wk[t] = wk[i*2+t];
  } else {
    for (int k = t; k < 512; k += kTPB) {
      int d = k >> 5, c = k & 31;
      g_a0s.Wq[k] = Wqkv[d*96 + c];
    }
    if (t < 16) { g_a0s.ln1g[t] = ln1g[t]; g_a0s.ln1b[t] = ln1b[t]; }
    if (t < 4)  g_a0s.wq[t] = wq[t];
    for (int k = t; k < kBot*16; k += kTPB) g_gls.Wemb[k] = Wemb[k];
    if (t < 16) { g_gls.bemb[t] = bemb[t]; g_gls.Wout[t] = Wout[t]; }
    if (t == 0) g_gls.bout[0] = bout[0];
  }
}

// ---------------- fused embed + stage-A(layer 0), 2 tokens/thread ----------------
__global__ void __launch_bounds__(kTPB) fusedEmbedA_kernel(const float* __restrict__ corr) {
  int b = blockIdx.x / kBPB;
  int blk = blockIdx.x % kBPB;
  int t = threadIdx.x;
  int n0 = blk * kTokB + t;
  int n1 = n0 + kTPB;
  bool a0f = n0 < kN, a1f = n1 < kN;
  float x0[16], x1[16];
  const float* cbase = corr + (size_t)b * kBot * kN;
  {
    u64 acc0[8], acc1[8];
#pragma unroll
    for (int m = 0; m < 4; m++) {
      u64 w0, w1; ldc4(&cG.bemb[4*m], w0, w1);
      acc0[2*m] = w0; acc0[2*m+1] = w1;
      acc1[2*m] = w0; acc1[2*m+1] = w1;
    }
#pragma unroll 13
    for (int c = 0; c < kBot; c++) {
      const float* cp = cbase + (size_t)c * kN;
      float v0 = a0f ? fmaxf(cp[n0], 0.f) : 0.f;
      float v1 = a1f ? fmaxf(cp[n1], 0.f) : 0.f;
      u64 vv0 = pack2(v0, v0);
      u64 vv1 = pack2(v1, v1);
#pragma unroll
      for (int m = 0; m < 4; m++) {
        u64 w0, w1; ldc4(&cG.Wemb[c*16 + 4*m], w0, w1);
        acc0[2*m]   = fma2(w0, vv0, acc0[2*m]);
        acc0[2*m+1] = fma2(w1, vv0, acc0[2*m+1]);
        acc1[2*m]   = fma2(w0, vv1, acc1[2*m]);
        acc1[2*m+1] = fma2(w1, vv1, acc1[2*m+1]);
      }
    }
#pragma unroll
    for (int m = 0; m < 8; m++) { unpack2(acc0[m], x0[2*m], x0[2*m+1]);
                                  unpack2(acc1[m], x1[2*m], x1[2*m+1]); }
    float4* xb = xblock(b, blk);
#pragma unroll
    for (int m = 0; m < 4; m++) {
      xb[m * kTokB + t]        = make_float4(x0[4*m], x0[4*m+1], x0[4*m+2], x0[4*m+3]);
      xb[m * kTokB + t + kTPB] = make_float4(x1[4*m], x1[4*m+1], x1[4*m+2], x1[4*m+3]);
    }
  }
  qstats_reduce2(x0, x1, a0f, a1f, n0, n1, cA.ln1g, cA.ln1b, cA.Wq, cA.wq,
                 g_partQ + (size_t)blockIdx.x * 40);
}

// ---------------- stage B: inline finalize-Q + k stats, 2 tokens/thread ----------------
__global__ void __launch_bounds__(kTPB) stageB_kernel() {
  __shared__ float sgq[32];
  int b = blockIdx.x / kBPB;
  int blk = blockIdx.x % kBPB;
  int t = threadIdx.x;
  finalize_inline(g_partQ, b, sgq);
  int n0 = blk * kTokB + t;
  int n1 = n0 + kTPB;
  bool a0f = n0 < kN, a1f = n1 < kN;
  float x0[16], x1[16];
  const float4* xb = xblock(b, blk);
#pragma unroll
  for (int m = 0; m < 4; m++) {
    float4 t4 = xb[m * kTokB + t];
    x0[4*m] = t4.x; x0[4*m+1] = t4.y; x0[4*m+2] = t4.z; x0[4*m+3] = t4.w;
    float4 t5 = xb[m * kTokB + t + kTPB];
    x1[4*m] = t5.x; x1[4*m+1] = t5.y; x1[4*m+2] = t5.z; x1[4*m+3] = t5.w;
  }
  float y0[16], y1[16];
  ln16(x0, cP.ln1g, cP.ln1b, y0);
  ln16(x1, cP.ln1g, cP.ln1b, y1);
  float4 r0 = g_rot[n0], r1 = g_rot[n1];
  float vals[40];
#pragma unroll
  for (int hp = 0; hp < 2; hp++) {
    u64 a0[8], a1[8];
#pragma unroll
    for (int m = 0; m < 8; m++) { a0[m] = 0ull; a1[m] = 0ull; }
#pragma unroll
    for (int d = 0; d < 16; d++) {
      u64 yd0 = pack2(y0[d], y0[d]);
      u64 yd1 = pack2(y1[d], y1[d]);
      const float* row = &cP.Wqkv[d*96 + 32 + hp*16];
#pragma unroll
      for (int h2 = 0; h2 < 4; h2++) {
        u64 w0, w1; ldc4(row + 4*h2, w0, w1);
        a0[2*h2]   = fma2(w0, yd0, a0[2*h2]);
        a0[2*h2+1] = fma2(w1, yd0, a0[2*h2+1]);
        a1[2*h2]   = fma2(w0, yd1, a1[2*h2]);
        a1[2*h2+1] = fma2(w1, yd1, a1[2*h2+1]);
      }
    }
#pragma unroll
    for (int h2 = 0; h2 < 4; h2++) {
      int h = hp * 4 + h2;
      float k0, k1, k2, k3, m0, m1, m2, m3;
      unpack2(a0[2*h2], k0, k1); unpack2(a0[2*h2+1], k2, k3);
      unpack2(a1[2*h2], m0, m1); unpack2(a1[2*h2+1], m2, m3);
      float q0 = k0*sgq[4*h+0] + k1*sgq[4*h+1];
      float q1 = k2*sgq[4*h+2] + k3*sgq[4*h+3];
      float s0 = m0*sgq[4*h+0] + m1*sgq[4*h+1];
      float s1 = m2*sgq[4*h+2] + m3*sgq[4*h+3];
      float lg0 = (q0*cP.wk[0] + q1*cP.wk[1]) * kScale;
      float lg1 = (s0*cP.wk[0] + s1*cP.wk[1]) * kScale;
      float e0 = a0f ? __expf(lg0) : 0.f;
      float e1 = a1f ? __expf(lg1) : 0.f;
      vals[h*5+0] = e0 + e1;
      vals[h*5+1] = e0*(k0*r0.x - k1*r0.y) + e1*(m0*r1.x - m1*r1.y);
      vals[h*5+2] = e0*(k1*r0.x + k0*r0.y) + e1*(m1*r1.x + m0*r1.y);
      vals[h*5+3] = e0*(k2*r0.z - k3*r0.w) + e1*(m2*r1.z - m3*r1.w);
      vals[h*5+4] = e0*(k3*r0.z + k2*r0.w) + e1*(m3*r1.z + m2*r1.w);
    }
  }
  reduce40_pairs(vals, g_partK + (size_t)blockIdx.x * 40);
}

// ---------------- fused: finalize-K + stage C + stage-A(next), 2 tokens/thread ----------------
__global__ void __launch_bounds__(kTPB, 2) fusedCA_kernel(float* __restrict__ out,
                                                          int last, int do_stats) {
  __shared__ float sgk[32];
  int b = blockIdx.x / kBPB;
  int blk = blockIdx.x % kBPB;
  int t = threadIdx.x;
  finalize_inline(g_partK, b, sgk);
  int n0 = blk * kTokB + t;
  int n1 = n0 + kTPB;
  bool a0f = n0 < kN, a1f = n1 < kN;
  float4* xb = xblock(b, blk);
  float x0[16], x1[16];
#pragma unroll
  for (int m = 0; m < 4; m++) {
    float4 t4 = xb[m * kTokB + t];
    x0[4*m] = t4.x; x0[4*m+1] = t4.y; x0[4*m+2] = t4.z; x0[4*m+3] = t4.w;
    float4 t5 = xb[m * kTokB + t + kTPB];
    x1[4*m] = t5.x; x1[4*m+1] = t5.y; x1[4*m+2] = t5.z; x1[4*m+3] = t5.w;
  }
  float y0[16], y1[16];
  ln16(x0, cP.ln1g, cP.ln1b, y0);
  ln16(x1, cP.ln1g, cP.ln1b, y1);

  // ao = boP + y@WqWo + (v*gk pairs)@WrWo
  u64 ao0[8], ao1[8];
#pragma unroll
  for (int m = 0; m < 4; m++) {
    u64 w0, w1; ldc4(&cP.boP[4*m], w0, w1);
    ao0[2*m] = w0; ao0[2*m+1] = w1;
    ao1[2*m] = w0; ao1[2*m+1] = w1;
  }
#pragma unroll
  for (int d = 0; d < 16; d++) {
    u64 yd0 = pack2(y0[d], y0[d]);
    u64 yd1 = pack2(y1[d], y1[d]);
    const float* row = &cP.WqWo[d*16];
#pragma unroll
    for (int m = 0; m < 4; m++) {
      u64 w0, w1; ldc4(row + 4*m, w0, w1);
      ao0[2*m]   = fma2(w0, yd0, ao0[2*m]);
      ao0[2*m+1] = fma2(w1, yd0, ao0[2*m+1]);
      ao1[2*m]   = fma2(w0, yd1, ao1[2*m]);
      ao1[2*m+1] = fma2(w1, yd1, ao1[2*m+1]);
    }
  }
  // v-GEMM in 2 head-quad passes; fold u into WrWo immediately
#pragma unroll
  for (int hp = 0; hp < 2; hp++) {
    u64 av0[8], av1[8];
#pragma unroll
    for (int m = 0; m < 8; m++) { av0[m] = 0ull; av1[m] = 0ull; }
#pragma unroll
    for (int d = 0; d < 16; d++) {
      u64 yd0 = pack2(y0[d], y0[d]);
      u64 yd1 = pack2(y1[d], y1[d]);
      const float* row = &cP.Wqkv[d*96 + 64 + hp*16];
#pragma unroll
      for (int h2 = 0; h2 < 4; h2++) {
        u64 w0, w1; ldc4(row + 4*h2, w0, w1);
        av0[2*h2]   = fma2(w0, yd0, av0[2*h2]);
        av0[2*h2+1] = fma2(w1, yd0, av0[2*h2+1]);
        av1[2*h2]   = fma2(w0, yd1, av1[2*h2]);
        av1[2*h2+1] = fma2(w1, yd1, av1[2*h2+1]);
      }
    }
#pragma unroll
    for (int h2 = 0; h2 < 4; h2++) {
      int h = hp * 4 + h2;
      float v0, v1, v2, v3, w0f, w1f, w2f, w3f;
      unpack2(av0[2*h2], v0, v1); unpack2(av0[2*h2+1], v2, v3);
      unpack2(av1[2*h2], w0f, w1f); unpack2(av1[2*h2+1], w2f, w3f);
      float u00 = v0*sgk[4*h+0] + v1*sgk[4*h+1];
      float u01 = v2*sgk[4*h+2] + v3*sgk[4*h+3];
      float u10 = w0f*sgk[4*h+0] + w1f*sgk[4*h+1];
      float u11 = w2f*sgk[4*h+2] + w3f*sgk[4*h+3];
#pragma unroll
      for (int p = 0; p < 2; p++) {
        u64 uc0 = pack2(p ? u01 : u00, p ? u01 : u00);
        u64 uc1 = pack2(p ? u11 : u10, p ? u11 : u10);
        const float* row = &cP.WrWo[(h*2 + p)*16];
#pragma unroll
        for (int m = 0; m < 4; m++) {
          u64 w0, w1; ldc4(row + 4*m, w0, w1);
          ao0[2*m]   = fma2(w0, uc0, ao0[2*m]);
          ao0[2*m+1] = fma2(w1, uc0, ao0[2*m+1]);
          ao1[2*m]   = fma2(w0, uc1, ao1[2*m]);
          ao1[2*m+1] = fma2(w1, uc1, ao1[2*m+1]);
        }
      }
    }
  }
#pragma unroll
  for (int m = 0; m < 8; m++) {
    float p0, p1; unpack2(ao0[m], p0, p1);
    x0[2*m] += p0; x0[2*m+1] += p1;
    unpack2(ao1[m], p0, p1);
    x1[2*m] += p0; x1[2*m+1] += p1;
  }

  // FF: LN2 then 4 chunks of 16 hidden
  float y20[16], y21[16];
  ln16(x0, cP.ln2g, cP.ln2b, y20);
  ln16(x1, cP.ln2g, cP.ln2b, y21);
  u64 a20[8], a21[8];
#pragma unroll
  for (int m = 0; m < 4; m++) {
    u64 w0, w1; ldc4(&cP.B2[4*m], w0, w1);
    a20[2*m] = w0; a20[2*m+1] = w1;
    a21[2*m] = w0; a21[2*m+1] = w1;
  }
#pragma unroll
  for (int jc = 0; jc < 4; jc++) {
    u64 hh0[8], hh1[8];
#pragma unroll
    for (int m = 0; m < 4; m++) {
      u64 w0, w1; ldc4(&cP.B1[jc*16 + 4*m], w0, w1);
      hh0[2*m] = w0; hh0[2*m+1] = w1;
      hh1[2*m] = w0; hh1[2*m+1] = w1;
    }
#pragma unroll
    for (int d = 0; d < 16; d++) {
      u64 yd0 = pack2(y20[d], y20[d]);
      u64 yd1 = pack2(y21[d], y21[d]);
      const float* row = &cP.W1[d*64 + jc*16];
#pragma unroll
      for (int m = 0; m < 4; m++) {
        u64 w0, w1; ldc4(row + 4*m, w0, w1);
        hh0[2*m]   = fma2(w0, yd0, hh0[2*m]);
        hh0[2*m+1] = fma2(w1, yd0, hh0[2*m+1]);
        hh1[2*m]   = fma2(w0, yd1, hh1[2*m]);
        hh1[2*m+1] = fma2(w1, yd1, hh1[2*m+1]);
      }
    }
#pragma unroll
    for (int m = 0; m < 8; m++) {
      float p00, p01, p10, p11;
      unpack2(hh0[m], p00, p01);
      unpack2(hh1[m], p10, p11);
      float g00 = gelu_fast(p00), g01 = gelu_fast(p01);
      float g10 = gelu_fast(p10), g11 = gelu_fast(p11);
      int j0 = jc*16 + 2*m;
#pragma unroll
      for (int jj = 0; jj < 2; jj++) {
        u64 h0 = pack2(jj ? g01 : g00, jj ? g01 : g00);
        u64 h1 = pack2(jj ? g11 : g10, jj ? g11 : g10);
        const float* w2r = &cP.W2[(j0 + jj)*16];
#pragma unroll
        for (int mm = 0; mm < 4; mm++) {
          u64 w0, w1; ldc4(w2r + 4*mm, w0, w1);
          a20[2*mm]   = fma2(w0, h0, a20[2*mm]);
          a20[2*mm+1] = fma2(w1, h0, a20[2*mm+1]);
          a21[2*mm]   = fma2(w0, h1, a21[2*mm]);
          a21[2*mm+1] = fma2(w1, h1, a21[2*mm+1]);
        }
      }
    }
  }
#pragma unroll
  for (int m = 0; m < 8; m++) {
    float p0, p1; unpack2(a20[m], p0, p1);
    x0[2*m] += p0; x0[2*m+1] += p1;
    unpack2(a21[m], p0, p1);
    x1[2*m] += p0; x1[2*m+1] += p1;
  }

  if (last) {
    float o0 = cG.bout[0], o1 = cG.bout[0];
#pragma unroll
    for (int d = 0; d < 16; d++) {
      o0 = fmaf(x0[d], cG.Wout[d], o0);
      o1 = fmaf(x1[d], cG.Wout[d], o1);
    }
    if (a0f) out[(size_t)b * kN + n0] = o0;
    if (a1f) out[(size_t)b * kN + n1] = o1;
  } else {
#pragma unroll
    for (int m = 0; m < 4; m++) {
      xb[m * kTokB + t]        = make_float4(x0[4*m], x0[4*m+1], x0[4*m+2], x0[4*m+3]);
      xb[m * kTokB + t + kTPB] = make_float4(x1[4*m], x1[4*m+1], x1[4*m+2], x1[4*m+3]);
    }
  }
  if (do_stats) {
    qstats_reduce2(x0, x1, a0f, a1f, n0, n1, cP.nLn1g, cP.nLn1b, cP.nWq,
                   cP.nWqlog, g_partQ + (size_t)blockIdx.x * 40);
  }
}

// ---------------- host launcher ----------------
extern "C" void kernel_launch(void* const* d_in, const int* in_sizes, int n_in,
                              void* d_out, int out_size) {
  (void)in_sizes; (void)n_in; (void)out_size;
  const float* corr  = (const float*)d_in[0];
  const float* W_emb = (const float*)d_in[1];
  const float* b_emb = (const float*)d_in[2];
  const float* ln1_g = (const float*)d_in[3];
  const float* ln1_b = (const float*)d_in[4];
  const float* W_qkv = (const float*)d_in[5];
  const float* w_qlog= (const float*)d_in[6];
  const float* w_klog= (const float*)d_in[7];
  const float* W_r   = (const float*)d_in[8];
  const float* b_r   = (const float*)d_in[9];
  const float* W_o   = (const float*)d_in[10];
  const float* b_o   = (const float*)d_in[11];
  const float* ln2_g = (const float*)d_in[12];
  const float* ln2_b = (const float*)d_in[13];
  const float* W_ff1 = (const float*)d_in[14];
  const float* b_ff1 = (const float*)d_in[15];
  const float* W_ff2 = (const float*)d_in[16];
  const float* b_ff2 = (const float*)d_in[17];
  const float* W_out = (const float*)d_in[18];
  const float* b_out = (const float*)d_in[19];
  float* out = (float*)d_out;

  rotprep_kernel<<<(kNP + kTPB - 1) / kTPB, kTPB>>>();
  gather_kernel<<<kL + 1, kTPB>>>(W_qkv, ln1_g, ln1_b, w_qlog, w_klog, W_r,
                                  b_r, W_o, b_o, ln2_g, ln2_b, W_ff1, b_ff1,
                                  W_ff2, b_ff2, W_emb, b_emb, W_out, b_out);

  void *pBanks = nullptr, *pA0 = nullptr, *pGl = nullptr;
  cudaGetSymbolAddress(&pBanks, g_banks);
  cudaGetSymbolAddress(&pA0, g_a0s);
  cudaGetSymbolAddress(&pGl, g_gls);

  cudaMemcpyToSymbolAsync(cG, pGl, sizeof(CGlob), 0, cudaMemcpyDeviceToDevice, 0);
  cudaMemcpyToSymbolAsync(cA, pA0, sizeof(CA0), 0, cudaMemcpyDeviceToDevice, 0);
  cudaMemcpyToSymbolAsync(cP, pBanks, sizeof(CParams), 0,
                          cudaMemcpyDeviceToDevice, 0);

  fusedEmbedA_kernel<<<kGrid, kTPB>>>(corr);

  for (int i = 0; i < kL; i++) {
    stageB_kernel<<<kGrid, kTPB>>>();
    fusedCA_kernel<<<kGrid, kTPB>>>(out, (i == kL - 1) ? 1 : 0,
                                    (i < kL - 1) ? 1 : 0);
    if (i + 1 < kL) {
      cudaMemcpyToSymbolAsync(
          cP, (const char*)pBanks + (size_t)(i + 1) * sizeof(CParams),
          sizeof(CParams), 0, cudaMemcpyDeviceToDevice, 0);
    }
  }
}

// round 10
// speedup vs baseline: 2.8964x; 2.8964x over previous
#include <cuda_runtime.h>
#include <math.h>

// ---------------- problem constants ----------------
namespace {
constexpr int kN   = 50625;          // SIDE^4
constexpr int kB   = 16;             // batch
constexpr int kBot = 26;
constexpr int kL   = 6;
constexpr int kTPB = 256;
constexpr int kBPB = (kN + kTPB - 1) / kTPB;   // 198 blocks per batch
constexpr int kNP  = kBPB * kTPB;              // padded tokens (50688)
constexpr int kGrid = kB * kBPB;               // 3168
constexpr float kScale = 0.5f;                 // DH^-0.5
}

typedef unsigned long long u64;

// ---------------- parameter banks ----------------
struct alignas(16) CParams {
  float Wqkv[1536];                  // (16,96) natural [d][96]
  float WqWo[256];                   // folded Wq@Wo [d][16]
  float WrWo[256];                   // folded Wr@Wo [(h*2+p)][16]
  float W1[1024];                    // (16,64) natural [d][64]
  float W2[1024];                    // (64,16) natural [j][16]
  float ln1g[16], ln1b[16], ln2g[16], ln2b[16];
  float wk[2], pad0[2];
  float boP[16];                     // folded b_o + (b_r rows)@Wo
  float B1[64], B2[16];
  float nLn1g[16], nLn1b[16];
  float nWqlog[4], pad1[4];
  float nWq[512];                    // [d][32] q columns of layer i+1
};
struct alignas(16) CA0 {
  float ln1g[16], ln1b[16], wq[4], pad[4];
  float Wq[512];                     // [d][32]
};
struct alignas(16) CGlob {
  float Wemb[kBot * 16];
  float bemb[16], Wout[16], bout[4], pad[4];
};

__constant__ CParams cP;
__constant__ CA0 cA;
__constant__ CGlob cG;

// ---------------- scratch ----------------
// x blocked-SoA: [b][blk][m(0..3)][t(0..255)] as float4
__device__ float g_x[(size_t)kB * kBPB * 4 * kTPB * 4];
__device__ float4 g_rot[kNP];
__device__ float g_partQ[kGrid * 40];
__device__ float g_partK[kGrid * 40];
__device__ CParams g_banks[kL];
__device__ CA0 g_a0s;
__device__ CGlob g_gls;

// ---------------- packed f32x2 helpers ----------------
__device__ __forceinline__ u64 pack2(float lo, float hi) {
  u64 r; asm("mov.b64 %0,{%1,%2};" : "=l"(r) : "f"(lo), "f"(hi)); return r;
}
__device__ __forceinline__ void unpack2(u64 v, float& lo, float& hi) {
  asm("mov.b64 {%0,%1},%2;" : "=f"(lo), "=f"(hi) : "l"(v));
}
__device__ __forceinline__ u64 fma2(u64 a, u64 b, u64 c) {
  u64 d; asm("fma.rn.f32x2 %0,%1,%2,%3;" : "=l"(d) : "l"(a), "l"(b), "l"(c)); return d;
}
__device__ __forceinline__ void ldc4(const float* p, u64& lo, u64& hi) {
  ulonglong2 v = *reinterpret_cast<const ulonglong2*>(p);
  lo = v.x; hi = v.y;
}

// ---------------- scalar helpers ----------------
__device__ __forceinline__ void ln16(const float* x, const float* g,
                                     const float* bb, float* y) {
  float m = 0.f;
#pragma unroll
  for (int d = 0; d < 16; d++) m += x[d];
  m *= (1.f / 16.f);
  float v = 0.f;
#pragma unroll
  for (int d = 0; d < 16; d++) { float t = x[d] - m; v = fmaf(t, t, v); }
  v *= (1.f / 16.f);
  float r = rsqrtf(v + 1e-5f);
#pragma unroll
  for (int d = 0; d < 16; d++) y[d] = (x[d] - m) * r * g[d] + bb[d];
}

__device__ __forceinline__ void rot_cs(int n, float& c0, float& s0,
                                       float& c1, float& s1) {
  float nf = (float)n;
  float p0 = nf * 3.14159265358979323846f;
  float p1 = nf * 15.70796326794896619231f;
  double d0 = (double)p0 - (double)n * 3.14159265358979323846;
  double d1 = (double)p1 - (double)n * 15.70796326794896619231;
  float e0 = (float)d0, e1 = (float)d1;
  float sgn = (n & 1) ? -1.f : 1.f;
  c0 = sgn * (1.f - 0.5f * e0 * e0);
  s0 = sgn * e0 * (1.f - 0.1666666667f * e0 * e0);
  c1 = sgn * (1.f - 0.5f * e1 * e1);
  s1 = sgn * e1 * (1.f - 0.1666666667f * e1 * e1);
}

__device__ __forceinline__ float gelu_fast(float p) {
  float xs = p * 0.7071067811865475f;
  float ax = fabsf(xs);
  float t = __fdividef(1.f, fmaf(0.3275911f, ax, 1.f));
  float poly = t * fmaf(t, fmaf(t, fmaf(t, fmaf(t, 1.061405429f,
                   -1.453152027f), 1.421413741f), -0.284496736f),
                   0.254829592f);
  float e = __expf(-ax * ax);
  float er = 1.f - poly * e;
  er = copysignf(er, xs);
  return 0.5f * p * (1.f + er);
}

// block reduction of 40 per-thread floats via smem transpose (float4)
__device__ __forceinline__ void reduce40_pairs(const float* vals, float* partOut) {
  __shared__ float4 sT[10 * 257];
  __shared__ float sS[40][12];
  int t = threadIdx.x;
#pragma unroll
  for (int p = 0; p < 10; p++)
    sT[p * 257 + t] = make_float4(vals[4*p], vals[4*p+1], vals[4*p+2], vals[4*p+3]);
  __syncthreads();
  if (t < 120) {
    int p = t / 12, sl = t % 12;
    float s0 = 0.f, s1 = 0.f, s2 = 0.f, s3 = 0.f;
    const float4* row = &sT[p * 257];
    for (int i = sl; i < kTPB; i += 12) {
      float4 v = row[i];
      s0 += v.x; s1 += v.y; s2 += v.z; s3 += v.w;
    }
    sS[4*p+0][sl] = s0; sS[4*p+1][sl] = s1;
    sS[4*p+2][sl] = s2; sS[4*p+3][sl] = s3;
  }
  __syncthreads();
  if (t < 40) {
    float s = 0.f;
#pragma unroll
    for (int j = 0; j < 12; j++) s += sS[t][j];
    partOut[t] = s;
  }
}

// ---- split inline finalize: issue loads early, commit late ----
// phase A (no sync): per-thread strided accumulation, 4-way MLP
__device__ __forceinline__ float finalize_acc(const float* part, int b) {
  int t = threadIdx.x;
  float acc = 0.f;
  if (t < 240) {
    int k = t / 6, sl = t % 6;
    const float* pp = part + (size_t)b * kBPB * 40;
    float a0 = 0.f, a1 = 0.f, a2 = 0.f, a3 = 0.f;
#pragma unroll
    for (int j = 0; j < 8; j++) {
      a0 += pp[(sl + (j*4+0)*6)*40 + k];
      a1 += pp[(sl + (j*4+1)*6)*40 + k];
      a2 += pp[(sl + (j*4+2)*6)*40 + k];
      a3 += pp[(sl + (j*4+3)*6)*40 + k];
    }
    acc = ((a0 + a1) + (a2 + a3)) + pp[(sl + 192)*40 + k];
  }
  return acc;
}
// phase B: commit to smem, compute 32 softmax weights (two cheap syncs)
__device__ __forceinline__ void finalize_commit(float acc, float* sg32) {
  __shared__ float sf[40][6];
  int t = threadIdx.x;
  if (t < 240) sf[t/6][t%6] = acc;
  __syncthreads();
  if (t < 32) {
    int h = t >> 2, d = t & 3;
    float den = sf[h*5][0]+sf[h*5][1]+sf[h*5][2]+sf[h*5][3]+sf[h*5][4]+sf[h*5][5];
    int r = h*5 + 1 + d;
    float num = sf[r][0]+sf[r][1]+sf[r][2]+sf[r][3]+sf[r][4]+sf[r][5];
    sg32[t] = num / den;
  }
  __syncthreads();
}

__device__ __forceinline__ float4* xblock(int b, int blk) {
  return reinterpret_cast<float4*>(g_x) + ((size_t)(b * kBPB + blk) * 4) * kTPB;
}

// stage-A statistics: LN1 -> q (32 cols) -> rotary + q-logit softmax partials.
__device__ __forceinline__ void qstats_reduce(
    const float* x, bool active, int n,
    const float* lg, const float* lb, const float* Wq, const float* wql,
    float* partOut) {
  float y[16];
  ln16(x, lg, lb, y);
  float4 rt = g_rot[n];
  float vals[40];
#pragma unroll
  for (int hp = 0; hp < 2; hp++) {
    u64 a[8];
#pragma unroll
    for (int m = 0; m < 8; m++) a[m] = 0ull;
#pragma unroll
    for (int d = 0; d < 16; d++) {
      u64 yd = pack2(y[d], y[d]);
      const float* row = &Wq[d * 32 + hp * 16];
#pragma unroll
      for (int h2 = 0; h2 < 4; h2++) {
        u64 w0, w1; ldc4(row + 4 * h2, w0, w1);
        a[2*h2]   = fma2(w0, yd, a[2*h2]);
        a[2*h2+1] = fma2(w1, yd, a[2*h2+1]);
      }
    }
#pragma unroll
    for (int h2 = 0; h2 < 4; h2++) {
      int h = hp * 4 + h2;
      float q0, q1, q2, q3;
      unpack2(a[2*h2], q0, q1); unpack2(a[2*h2+1], q2, q3);
      float lgt = (q0*wql[0] + q1*wql[1] + q2*wql[2] + q3*wql[3]) * kScale;
      float e = active ? __expf(lgt) : 0.f;
      vals[h*5+0] = e;
      vals[h*5+1] = e * (q0*rt.x - q1*rt.y);
      vals[h*5+2] = e * (q1*rt.x + q0*rt.y);
      vals[h*5+3] = e * (q2*rt.z - q3*rt.w);
      vals[h*5+4] = e * (q3*rt.z + q2*rt.w);
    }
  }
  reduce40_pairs(vals, partOut);
}

// ---------------- prep kernels ----------------
__global__ void rotprep_kernel() {
  int n = blockIdx.x * kTPB + threadIdx.x;
  float c0, s0, c1, s1; rot_cs(n, c0, s0, c1, s1);
  g_rot[n] = make_float4(c0, s0, c1, s1);
}

__global__ void gather_kernel(
    const float* __restrict__ Wqkv, const float* __restrict__ ln1g,
    const float* __restrict__ ln1b, const float* __restrict__ wq,
    const float* __restrict__ wk, const float* __restrict__ Wr,
    const float* __restrict__ br, const float* __restrict__ Wo,
    const float* __restrict__ bo, const float* __restrict__ ln2g,
    const float* __restrict__ ln2b, const float* __restrict__ W1,
    const float* __restrict__ b1, const float* __restrict__ W2,
    const float* __restrict__ b2, const float* __restrict__ Wemb,
    const float* __restrict__ bemb, const float* __restrict__ Wout,
    const float* __restrict__ bout) {
  int i = blockIdx.x;
  int t = threadIdx.x;
  if (i < kL) {
    CParams* s = &g_banks[i];
    for (int k = t; k < 1536; k += kTPB) s->Wqkv[k] = Wqkv[i*1536 + k];
    for (int k = t; k < 1024; k += kTPB) s->W1[k]  = W1[i*1024 + k];
    for (int k = t; k < 1024; k += kTPB) s->W2[k]  = W2[i*1024 + k];
    {
      int d = t >> 4, e = t & 15;
      float acc = 0.f;
      for (int c = 0; c < 32; c++)
        acc += Wqkv[i*1536 + d*96 + c] * Wo[i*512 + c*16 + e];
      s->WqWo[t] = acc;
    }
    {
      int h = t >> 5, p = (t >> 4) & 1, e = t & 15;
      float acc = 0.f;
      for (int j = 0; j < 4; j++)
        acc += Wr[i*8 + p*4 + j] * Wo[i*512 + (4*h + j)*16 + e];
      s->WrWo[t] = acc;
    }
    if (t < 16) {
      float acc = bo[i*16 + t];
      for (int h = 0; h < 8; h++)
        for (int j = 0; j < 4; j++)
          acc += br[i*4 + j] * Wo[i*512 + (4*h + j)*16 + t];
      s->boP[t] = acc;
    }
    int jn = (i + 1 < kL) ? i + 1 : i;
    for (int k = t; k < 512; k += kTPB) {
      int d = k >> 5, c = k & 31;
      s->nWq[k] = Wqkv[jn*1536 + d*96 + c];
    }
    if (t < 16) {
      s->ln1g[t] = ln1g[i*16+t]; s->ln1b[t] = ln1b[i*16+t];
      s->ln2g[t] = ln2g[i*16+t]; s->ln2b[t] = ln2b[i*16+t];
      s->B2[t] = b2[i*16+t];
      s->nLn1g[t] = ln1g[jn*16+t]; s->nLn1b[t] = ln1b[jn*16+t];
    }
    if (t < 64) s->B1[t] = b1[i*64+t];
    if (t < 4)  s->nWqlog[t] = wq[jn*4+t];
    if (t < 2)  s->wk[t] = wk[i*2+t];
  } else {
    for (int k = t; k < 512; k += kTPB) {
      int d = k >> 5, c = k & 31;
      g_a0s.Wq[k] = Wqkv[d*96 + c];
    }
    if (t < 16) { g_a0s.ln1g[t] = ln1g[t]; g_a0s.ln1b[t] = ln1b[t]; }
    if (t < 4)  g_a0s.wq[t] = wq[t];
    for (int k = t; k < kBot*16; k += kTPB) g_gls.Wemb[k] = Wemb[k];
    if (t < 16) { g_gls.bemb[t] = bemb[t]; g_gls.Wout[t] = Wout[t]; }
    if (t == 0) g_gls.bout[0] = bout[0];
  }
}

// ---------------- fused embed + stage-A(layer 0) ----------------
__global__ void __launch_bounds__(kTPB) fusedEmbedA_kernel(const float* __restrict__ corr) {
  int b = blockIdx.x / kBPB;
  int blk = blockIdx.x % kBPB;
  int t = threadIdx.x;
  int n = blk * kTPB + t;
  bool active = n < kN;
  float x[16];
  if (active) {
    u64 acc[8];
#pragma unroll
    for (int m = 0; m < 4; m++) ldc4(&cG.bemb[4*m], acc[2*m], acc[2*m+1]);
    const float* cp = corr + (size_t)b * kBot * kN + n;
#pragma unroll 13
    for (int c = 0; c < kBot; c++) {
      float v = fmaxf(cp[(size_t)c * kN], 0.f);
      u64 v2 = pack2(v, v);
#pragma unroll
      for (int m = 0; m < 4; m++) {
        u64 w0, w1; ldc4(&cG.Wemb[c*16 + 4*m], w0, w1);
        acc[2*m]   = fma2(w0, v2, acc[2*m]);
        acc[2*m+1] = fma2(w1, v2, acc[2*m+1]);
      }
    }
#pragma unroll
    for (int m = 0; m < 8; m++) unpack2(acc[m], x[2*m], x[2*m+1]);
  } else {
#pragma unroll
    for (int d = 0; d < 16; d++) x[d] = 0.f;
  }
  float4* xb = xblock(b, blk);
#pragma unroll
  for (int m = 0; m < 4; m++)
    xb[m * kTPB + t] = make_float4(x[4*m], x[4*m+1], x[4*m+2], x[4*m+3]);
  qstats_reduce(x, active, n, cA.ln1g, cA.ln1b, cA.Wq, cA.wq,
                g_partQ + (size_t)blockIdx.x * 40);
}

// ---------------- stage B: overlapped finalize-Q + k stats ----------------
__global__ void __launch_bounds__(kTPB) stageB_kernel() {
  __shared__ float sgq[32];
  int b = blockIdx.x / kBPB;
  int blk = blockIdx.x % kBPB;
  int t = threadIdx.x;
  // phase A: issue finalize loads (results consumed after overlap window)
  float facc = finalize_acc(g_partQ, b);
  int n = blk * kTPB + t;
  bool active = n < kN;
  float x[16];
  const float4* xb = xblock(b, blk);
#pragma unroll
  for (int m = 0; m < 4; m++) {
    float4 t4 = xb[m * kTPB + t];
    x[4*m] = t4.x; x[4*m+1] = t4.y; x[4*m+2] = t4.z; x[4*m+3] = t4.w;
  }
  float y[16];
  ln16(x, cP.ln1g, cP.ln1b, y);
  float4 rt = g_rot[n];
  float vals[40];
  // GEMM for head-quad 0 (no sgq needed) — overlaps finalize load latency
  u64 a[8];
#pragma unroll
  for (int m = 0; m < 8; m++) a[m] = 0ull;
#pragma unroll
  for (int d = 0; d < 16; d++) {
    u64 yd = pack2(y[d], y[d]);
    const float* row = &cP.Wqkv[d*96 + 32];
#pragma unroll
    for (int h2 = 0; h2 < 4; h2++) {
      u64 w0, w1; ldc4(row + 4*h2, w0, w1);
      a[2*h2]   = fma2(w0, yd, a[2*h2]);
      a[2*h2+1] = fma2(w1, yd, a[2*h2+1]);
    }
  }
  // phase B: commit finalize, get sgq
  finalize_commit(facc, sgq);
#pragma unroll
  for (int hp = 0; hp < 2; hp++) {
    if (hp == 1) {
#pragma unroll
      for (int m = 0; m < 8; m++) a[m] = 0ull;
#pragma unroll
      for (int d = 0; d < 16; d++) {
        u64 yd = pack2(y[d], y[d]);
        const float* row = &cP.Wqkv[d*96 + 32 + 16];
#pragma unroll
        for (int h2 = 0; h2 < 4; h2++) {
          u64 w0, w1; ldc4(row + 4*h2, w0, w1);
          a[2*h2]   = fma2(w0, yd, a[2*h2]);
          a[2*h2+1] = fma2(w1, yd, a[2*h2+1]);
        }
      }
    }
#pragma unroll
    for (int h2 = 0; h2 < 4; h2++) {
      int h = hp * 4 + h2;
      float k0, k1, k2v, k3;
      unpack2(a[2*h2], k0, k1); unpack2(a[2*h2+1], k2v, k3);
      float p0 = k0*sgq[4*h+0] + k1*sgq[4*h+1];
      float p1 = k2v*sgq[4*h+2] + k3*sgq[4*h+3];
      float lgt = (p0*cP.wk[0] + p1*cP.wk[1]) * kScale;
      float e = active ? __expf(lgt) : 0.f;
      vals[h*5+0] = e;
      vals[h*5+1] = e * (k0*rt.x - k1*rt.y);
      vals[h*5+2] = e * (k1*rt.x + k0*rt.y);
      vals[h*5+3] = e * (k2v*rt.z - k3*rt.w);
      vals[h*5+4] = e * (k3*rt.z + k2v*rt.w);
    }
  }
  reduce40_pairs(vals, g_partK + (size_t)blockIdx.x * 40);
}

// ---------------- fused: overlapped finalize-K + stage C + stage-A(next) ----------------
__global__ void __launch_bounds__(kTPB) fusedCA_kernel(float* __restrict__ out,
                                                       int last, int do_stats) {
  __shared__ float sgk[32];
  int b = blockIdx.x / kBPB;
  int blk = blockIdx.x % kBPB;
  int t = threadIdx.x;
  // phase A: issue finalize loads
  float facc = finalize_acc(g_partK, b);
  int n = blk * kTPB + t;
  bool active = n < kN;
  float4* xb = xblock(b, blk);
  float x[16];
#pragma unroll
  for (int m = 0; m < 4; m++) {
    float4 t4 = xb[m * kTPB + t];
    x[4*m] = t4.x; x[4*m+1] = t4.y; x[4*m+2] = t4.z; x[4*m+3] = t4.w;
  }
  float y[16];
  ln16(x, cP.ln1g, cP.ln1b, y);

  // ao = boP + y@WqWo  (sgk-independent; overlaps finalize loads)
  u64 ao[8];
#pragma unroll
  for (int m = 0; m < 4; m++) ldc4(&cP.boP[4*m], ao[2*m], ao[2*m+1]);
#pragma unroll
  for (int d = 0; d < 16; d++) {
    u64 yd = pack2(y[d], y[d]);
    const float* row = &cP.WqWo[d*16];
#pragma unroll
    for (int m = 0; m < 4; m++) {
      u64 w0, w1; ldc4(row + 4*m, w0, w1);
      ao[2*m]   = fma2(w0, yd, ao[2*m]);
      ao[2*m+1] = fma2(w1, yd, ao[2*m+1]);
    }
  }
  // phase B: commit finalize, get sgk
  finalize_commit(facc, sgk);

  // v-GEMM in 2 head-quad passes; fold u into WrWo immediately
#pragma unroll
  for (int hp = 0; hp < 2; hp++) {
    u64 av[8];
#pragma unroll
    for (int m = 0; m < 8; m++) av[m] = 0ull;
#pragma unroll
    for (int d = 0; d < 16; d++) {
      u64 yd = pack2(y[d], y[d]);
      const float* row = &cP.Wqkv[d*96 + 64 + hp*16];
#pragma unroll
      for (int h2 = 0; h2 < 4; h2++) {
        u64 w0, w1; ldc4(row + 4*h2, w0, w1);
        av[2*h2]   = fma2(w0, yd, av[2*h2]);
        av[2*h2+1] = fma2(w1, yd, av[2*h2+1]);
      }
    }
#pragma unroll
    for (int h2 = 0; h2 < 4; h2++) {
      int h = hp * 4 + h2;
      float v0, v1, v2, v3;
      unpack2(av[2*h2], v0, v1); unpack2(av[2*h2+1], v2, v3);
      float u0 = v0*sgk[4*h+0] + v1*sgk[4*h+1];
      float u1 = v2*sgk[4*h+2] + v3*sgk[4*h+3];
#pragma unroll
      for (int p = 0; p < 2; p++) {
        float uv = p ? u1 : u0;
        u64 uc = pack2(uv, uv);
        const float* row = &cP.WrWo[(h*2 + p)*16];
#pragma unroll
        for (int m = 0; m < 4; m++) {
          u64 w0, w1; ldc4(row + 4*m, w0, w1);
          ao[2*m]   = fma2(w0, uc, ao[2*m]);
          ao[2*m+1] = fma2(w1, uc, ao[2*m+1]);
        }
      }
    }
  }
#pragma unroll
  for (int m = 0; m < 8; m++) {
    float a0, a1; unpack2(ao[m], a0, a1);
    x[2*m] += a0; x[2*m+1] += a1;
  }

  // FF block, 2 chunks of 32 hidden units
  float y2[16];
  ln16(x, cP.ln2g, cP.ln2b, y2);
  u64 a2[8];
#pragma unroll
  for (int m = 0; m < 4; m++) ldc4(&cP.B2[4*m], a2[2*m], a2[2*m+1]);
#pragma unroll
  for (int jc = 0; jc < 2; jc++) {
    u64 hh[16];
#pragma unroll
    for (int m = 0; m < 8; m++) ldc4(&cP.B1[jc*32 + 4*m], hh[2*m], hh[2*m+1]);
#pragma unroll
    for (int d = 0; d < 16; d++) {
      u64 yd = pack2(y2[d], y2[d]);
      const float* row = &cP.W1[d*64 + jc*32];
#pragma unroll
      for (int m = 0; m < 8; m++) {
        u64 w0, w1; ldc4(row + 4*m, w0, w1);
        hh[2*m]   = fma2(w0, yd, hh[2*m]);
        hh[2*m+1] = fma2(w1, yd, hh[2*m+1]);
      }
    }
#pragma unroll
    for (int m = 0; m < 16; m++) {
      float p0, p1; unpack2(hh[m], p0, p1);
      float g0 = gelu_fast(p0);
      float g1 = gelu_fast(p1);
      int j0 = jc*32 + 2*m;
      u64 h0 = pack2(g0, g0);
      const float* w2r = &cP.W2[j0*16];
#pragma unroll
      for (int mm = 0; mm < 4; mm++) {
        u64 w0, w1; ldc4(w2r + 4*mm, w0, w1);
        a2[2*mm]   = fma2(w0, h0, a2[2*mm]);
        a2[2*mm+1] = fma2(w1, h0, a2[2*mm+1]);
      }
      u64 h1 = pack2(g1, g1);
      w2r += 16;
#pragma unroll
      for (int mm = 0; mm < 4; mm++) {
        u64 w0, w1; ldc4(w2r + 4*mm, w0, w1);
        a2[2*mm]   = fma2(w0, h1, a2[2*mm]);
        a2[2*mm+1] = fma2(w1, h1, a2[2*mm+1]);
      }
    }
  }
#pragma unroll
  for (int m = 0; m < 8; m++) {
    float a0, a1; unpack2(a2[m], a0, a1);
    x[2*m] += a0; x[2*m+1] += a1;
  }

  if (last) {
    if (active) {
      float o = cG.bout[0];
#pragma unroll
      for (int d = 0; d < 16; d++) o = fmaf(x[d], cG.Wout[d], o);
      out[(size_t)b * kN + n] = o;
    }
  } else {
#pragma unroll
    for (int m = 0; m < 4; m++)
      xb[m * kTPB + t] = make_float4(x[4*m], x[4*m+1], x[4*m+2], x[4*m+3]);
  }
  if (do_stats) {
    qstats_reduce(x, active, n, cP.nLn1g, cP.nLn1b, cP.nWq, cP.nWqlog,
                  g_partQ + (size_t)blockIdx.x * 40);
  }
}

// ---------------- host launcher ----------------
extern "C" void kernel_launch(void* const* d_in, const int* in_sizes, int n_in,
                              void* d_out, int out_size) {
  (void)in_sizes; (void)n_in; (void)out_size;
  const float* corr  = (const float*)d_in[0];
  const float* W_emb = (const float*)d_in[1];
  const float* b_emb = (const float*)d_in[2];
  const float* ln1_g = (const float*)d_in[3];
  const float* ln1_b = (const float*)d_in[4];
  const float* W_qkv = (const float*)d_in[5];
  const float* w_qlog= (const float*)d_in[6];
  const float* w_klog= (const float*)d_in[7];
  const float* W_r   = (const float*)d_in[8];
  const float* b_r   = (const float*)d_in[9];
  const float* W_o   = (const float*)d_in[10];
  const float* b_o   = (const float*)d_in[11];
  const float* ln2_g = (const float*)d_in[12];
  const float* ln2_b = (const float*)d_in[13];
  const float* W_ff1 = (const float*)d_in[14];
  const float* b_ff1 = (const float*)d_in[15];
  const float* W_ff2 = (const float*)d_in[16];
  const float* b_ff2 = (const float*)d_in[17];
  const float* W_out = (const float*)d_in[18];
  const float* b_out = (const float*)d_in[19];
  float* out = (float*)d_out;

  rotprep_kernel<<<kBPB, kTPB>>>();
  gather_kernel<<<kL + 1, kTPB>>>(W_qkv, ln1_g, ln1_b, w_qlog, w_klog, W_r,
                                  b_r, W_o, b_o, ln2_g, ln2_b, W_ff1, b_ff1,
                                  W_ff2, b_ff2, W_emb, b_emb, W_out, b_out);

  void *pBanks = nullptr, *pA0 = nullptr, *pGl = nullptr;
  cudaGetSymbolAddress(&pBanks, g_banks);
  cudaGetSymbolAddress(&pA0, g_a0s);
  cudaGetSymbolAddress(&pGl, g_gls);

  cudaMemcpyToSymbolAsync(cG, pGl, sizeof(CGlob), 0, cudaMemcpyDeviceToDevice, 0);
  cudaMemcpyToSymbolAsync(cA, pA0, sizeof(CA0), 0, cudaMemcpyDeviceToDevice, 0);
  cudaMemcpyToSymbolAsync(cP, pBanks, sizeof(CParams), 0,
                          cudaMemcpyDeviceToDevice, 0);

  fusedEmbedA_kernel<<<kGrid, kTPB>>>(corr);

  for (int i = 0; i < kL; i++) {
    stageB_kernel<<<kGrid, kTPB>>>();
    fusedCA_kernel<<<kGrid, kTPB>>>(out, (i == kL - 1) ? 1 : 0,
                                    (i < kL - 1) ? 1 : 0);
    if (i + 1 < kL) {
      cudaMemcpyToSymbolAsync(
          cP, (const char*)pBanks + (size_t)(i + 1) * sizeof(CParams),
          sizeof(CParams), 0, cudaMemcpyDeviceToDevice, 0);
    }
  }
}

// round 12
// speedup vs baseline: 2.9178x; 1.0074x over previous
#include <cuda_runtime.h>
#include <math.h>

// ---------------- problem constants ----------------
namespace {
constexpr int kN   = 50625;          // SIDE^4
constexpr int kB   = 16;             // batch
constexpr int kBot = 26;
constexpr int kL   = 6;
constexpr int kTPB = 256;
constexpr int kBPB = (kN + kTPB - 1) / kTPB;   // 198 blocks per batch
constexpr int kNP  = kBPB * kTPB;              // padded tokens (50688)
constexpr int kGrid = kB * kBPB;               // 3168
constexpr float kScale = 0.5f;                 // DH^-0.5
}

typedef unsigned long long u64;

// ---------------- parameter banks ----------------
struct alignas(16) CParams {
  float Wqkv[1536];                  // (16,96) natural [d][96]
  float WqWo[256];                   // folded Wq@Wo [d][16]
  float WrWo[256];                   // folded Wr@Wo [(h*2+p)][16]
  float W1[1024];                    // (16,64) natural [d][64]
  float W2[1024];                    // (64,16) natural [j][16]
  float ln1g[16], ln1b[16], ln2g[16], ln2b[16];
  float wk[2], pad0[2];
  float boP[16];                     // folded b_o + (b_r rows)@Wo
  float B1[64], B2[16];
  float nLn1g[16], nLn1b[16];
  float nWqlog[4], pad1[4];
  float nWq[512];                    // [d][32] q columns of layer i+1
};
struct alignas(16) CA0 {
  float ln1g[16], ln1b[16], wq[4], pad[4];
  float Wq[512];                     // [d][32]
};
struct alignas(16) CGlob {
  float Wemb[kBot * 16];
  float bemb[16], Wout[16], bout[4], pad[4];
};

__constant__ CParams cP;
__constant__ CA0 cA;
__constant__ CGlob cG;

// ---------------- scratch ----------------
// x blocked-SoA: [b][blk][m(0..3)][t(0..255)] as float4
__device__ float g_x[(size_t)kB * kBPB * 4 * kTPB * 4];
__device__ float4 g_rot[kNP];
__device__ float g_partQ[kGrid * 40];
__device__ float g_partK[kGrid * 40];
__device__ CParams g_banks[kL];
__device__ CA0 g_a0s;
__device__ CGlob g_gls;

// ---------------- packed f32x2 helpers ----------------
__device__ __forceinline__ u64 pack2(float lo, float hi) {
  u64 r; asm("mov.b64 %0,{%1,%2};" : "=l"(r) : "f"(lo), "f"(hi)); return r;
}
__device__ __forceinline__ void unpack2(u64 v, float& lo, float& hi) {
  asm("mov.b64 {%0,%1},%2;" : "=f"(lo), "=f"(hi) : "l"(v));
}
__device__ __forceinline__ u64 fma2(u64 a, u64 b, u64 c) {
  u64 d; asm("fma.rn.f32x2 %0,%1,%2,%3;" : "=l"(d) : "l"(a), "l"(b), "l"(c)); return d;
}
__device__ __forceinline__ void ldc4(const float* p, u64& lo, u64& hi) {
  ulonglong2 v = *reinterpret_cast<const ulonglong2*>(p);
  lo = v.x; hi = v.y;
}

// ---------------- scalar helpers ----------------
__device__ __forceinline__ void ln16(const float* x, const float* g,
                                     const float* bb, float* y) {
  float m = 0.f;
#pragma unroll
  for (int d = 0; d < 16; d++) m += x[d];
  m *= (1.f / 16.f);
  float v = 0.f;
#pragma unroll
  for (int d = 0; d < 16; d++) { float t = x[d] - m; v = fmaf(t, t, v); }
  v *= (1.f / 16.f);
  float r = rsqrtf(v + 1e-5f);
#pragma unroll
  for (int d = 0; d < 16; d++) y[d] = (x[d] - m) * r * g[d] + bb[d];
}

__device__ __forceinline__ void rot_cs(int n, float& c0, float& s0,
                                       float& c1, float& s1) {
  float nf = (float)n;
  float p0 = nf * 3.14159265358979323846f;
  float p1 = nf * 15.70796326794896619231f;
  double d0 = (double)p0 - (double)n * 3.14159265358979323846;
  double d1 = (double)p1 - (double)n * 15.70796326794896619231;
  float e0 = (float)d0, e1 = (float)d1;
  float sgn = (n & 1) ? -1.f : 1.f;
  c0 = sgn * (1.f - 0.5f * e0 * e0);
  s0 = sgn * e0 * (1.f - 0.1666666667f * e0 * e0);
  c1 = sgn * (1.f - 0.5f * e1 * e1);
  s1 = sgn * e1 * (1.f - 0.1666666667f * e1 * e1);
}

__device__ __forceinline__ float gelu_fast(float p) {
  float xs = p * 0.7071067811865475f;
  float ax = fabsf(xs);
  float t = __fdividef(1.f, fmaf(0.3275911f, ax, 1.f));
  float poly = t * fmaf(t, fmaf(t, fmaf(t, fmaf(t, 1.061405429f,
                   -1.453152027f), 1.421413741f), -0.284496736f),
                   0.254829592f);
  float e = __expf(-ax * ax);
  float er = 1.f - poly * e;
  er = copysignf(er, xs);
  return 0.5f * p * (1.f + er);
}

// ---- split block reduction: store 20 vals per half, finish once ----
__device__ __forceinline__ void red_store(float4* sT, const float* v20, int half) {
  int t = threadIdx.x;
#pragma unroll
  for (int p = 0; p < 5; p++)
    sT[(half*5 + p) * 257 + t] =
        make_float4(v20[4*p], v20[4*p+1], v20[4*p+2], v20[4*p+3]);
}
__device__ __forceinline__ void red_finish(const float4* sT, float* partOut) {
  __shared__ float sS[40][12];
  int t = threadIdx.x;
  __syncthreads();
  if (t < 120) {
    int p = t / 12, sl = t % 12;
    float s0 = 0.f, s1 = 0.f, s2 = 0.f, s3 = 0.f;
    const float4* row = &sT[p * 257];
    for (int i = sl; i < kTPB; i += 12) {
      float4 v = row[i];
      s0 += v.x; s1 += v.y; s2 += v.z; s3 += v.w;
    }
    sS[4*p+0][sl] = s0; sS[4*p+1][sl] = s1;
    sS[4*p+2][sl] = s2; sS[4*p+3][sl] = s3;
  }
  __syncthreads();
  if (t < 40) {
    float s = 0.f;
#pragma unroll
    for (int j = 0; j < 12; j++) s += sS[t][j];
    partOut[t] = s;
  }
}

// ---- split inline finalize: issue loads early, commit late ----
__device__ __forceinline__ float finalize_acc(const float* part, int b) {
  int t = threadIdx.x;
  float acc = 0.f;
  if (t < 240) {
    int k = t / 6, sl = t % 6;
    const float* pp = part + (size_t)b * kBPB * 40;
    float a0 = 0.f, a1 = 0.f, a2 = 0.f, a3 = 0.f;
#pragma unroll
    for (int j = 0; j < 8; j++) {
      a0 += pp[(sl + (j*4+0)*6)*40 + k];
      a1 += pp[(sl + (j*4+1)*6)*40 + k];
      a2 += pp[(sl + (j*4+2)*6)*40 + k];
      a3 += pp[(sl + (j*4+3)*6)*40 + k];
    }
    acc = ((a0 + a1) + (a2 + a3)) + pp[(sl + 192)*40 + k];
  }
  return acc;
}
__device__ __forceinline__ void finalize_commit(float acc, float* sg32) {
  __shared__ float sf[40][6];
  int t = threadIdx.x;
  if (t < 240) sf[t/6][t%6] = acc;
  __syncthreads();
  if (t < 32) {
    int h = t >> 2, d = t & 3;
    float den = sf[h*5][0]+sf[h*5][1]+sf[h*5][2]+sf[h*5][3]+sf[h*5][4]+sf[h*5][5];
    int r = h*5 + 1 + d;
    float num = sf[r][0]+sf[r][1]+sf[r][2]+sf[r][3]+sf[r][4]+sf[r][5];
    sg32[t] = num / den;
  }
  __syncthreads();
}

__device__ __forceinline__ float4* xblock(int b, int blk) {
  return reinterpret_cast<float4*>(g_x) + ((size_t)(b * kBPB + blk) * 4) * kTPB;
}

// stage-A statistics: LN1 -> q (32 cols) -> rotary + q-logit softmax partials.
__device__ __forceinline__ void qstats_reduce(
    float4* sT, const float* x, bool active, int n,
    const float* lg, const float* lb, const float* Wq, const float* wql,
    float* partOut) {
  float y[16];
  ln16(x, lg, lb, y);
  float4 rt = g_rot[n];
#pragma unroll
  for (int hp = 0; hp < 2; hp++) {
    u64 a[8];
#pragma unroll
    for (int m = 0; m < 8; m++) a[m] = 0ull;
#pragma unroll
    for (int d = 0; d < 16; d++) {
      u64 yd = pack2(y[d], y[d]);
      const float* row = &Wq[d * 32 + hp * 16];
#pragma unroll
      for (int h2 = 0; h2 < 4; h2++) {
        u64 w0, w1; ldc4(row + 4 * h2, w0, w1);
        a[2*h2]   = fma2(w0, yd, a[2*h2]);
        a[2*h2+1] = fma2(w1, yd, a[2*h2+1]);
      }
    }
    float v20[20];
#pragma unroll
    for (int h2 = 0; h2 < 4; h2++) {
      float q0, q1, q2, q3;
      unpack2(a[2*h2], q0, q1); unpack2(a[2*h2+1], q2, q3);
      float lgt = (q0*wql[0] + q1*wql[1] + q2*wql[2] + q3*wql[3]) * kScale;
      float e = active ? __expf(lgt) : 0.f;
      v20[h2*5+0] = e;
      v20[h2*5+1] = e * (q0*rt.x - q1*rt.y);
      v20[h2*5+2] = e * (q1*rt.x + q0*rt.y);
      v20[h2*5+3] = e * (q2*rt.z - q3*rt.w);
      v20[h2*5+4] = e * (q3*rt.z + q2*rt.w);
    }
    red_store(sT, v20, hp);
  }
  red_finish(sT, partOut);
}

// ---------------- prep kernels ----------------
__global__ void rotprep_kernel() {
  int n = blockIdx.x * kTPB + threadIdx.x;
  float c0, s0, c1, s1; rot_cs(n, c0, s0, c1, s1);
  g_rot[n] = make_float4(c0, s0, c1, s1);
}

__global__ void gather_kernel(
    const float* __restrict__ Wqkv, const float* __restrict__ ln1g,
    const float* __restrict__ ln1b, const float* __restrict__ wq,
    const float* __restrict__ wk, const float* __restrict__ Wr,
    const float* __restrict__ br, const float* __restrict__ Wo,
    const float* __restrict__ bo, const float* __restrict__ ln2g,
    const float* __restrict__ ln2b, const float* __restrict__ W1,
    const float* __restrict__ b1, const float* __restrict__ W2,
    const float* __restrict__ b2, const float* __restrict__ Wemb,
    const float* __restrict__ bemb, const float* __restrict__ Wout,
    const float* __restrict__ bout) {
  int i = blockIdx.x;
  int t = threadIdx.x;
  if (i < kL) {
    CParams* s = &g_banks[i];
    for (int k = t; k < 1536; k += kTPB) s->Wqkv[k] = Wqkv[i*1536 + k];
    for (int k = t; k < 1024; k += kTPB) s->W1[k]  = W1[i*1024 + k];
    for (int k = t; k < 1024; k += kTPB) s->W2[k]  = W2[i*1024 + k];
    {
      int d = t >> 4, e = t & 15;
      float acc = 0.f;
      for (int c = 0; c < 32; c++)
        acc += Wqkv[i*1536 + d*96 + c] * Wo[i*512 + c*16 + e];
      s->WqWo[t] = acc;
    }
    {
      int h = t >> 5, p = (t >> 4) & 1, e = t & 15;
      float acc = 0.f;
      for (int j = 0; j < 4; j++)
        acc += Wr[i*8 + p*4 + j] * Wo[i*512 + (4*h + j)*16 + e];
      s->WrWo[t] = acc;
    }
    if (t < 16) {
      float acc = bo[i*16 + t];
      for (int h = 0; h < 8; h++)
        for (int j = 0; j < 4; j++)
          acc += br[i*4 + j] * Wo[i*512 + (4*h + j)*16 + t];
      s->boP[t] = acc;
    }
    int jn = (i + 1 < kL) ? i + 1 : i;
    for (int k = t; k < 512; k += kTPB) {
      int d = k >> 5, c = k & 31;
      s->nWq[k] = Wqkv[jn*1536 + d*96 + c];
    }
    if (t < 16) {
      s->ln1g[t] = ln1g[i*16+t]; s->ln1b[t] = ln1b[i*16+t];
      s->ln2g[t] = ln2g[i*16+t]; s->ln2b[t] = ln2b[i*16+t];
      s->B2[t] = b2[i*16+t];
      s->nLn1g[t] = ln1g[jn*16+t]; s->nLn1b[t] = ln1b[jn*16+t];
    }
    if (t < 64) s->B1[t] = b1[i*64+t];
    if (t < 4)  s->nWqlog[t] = wq[jn*4+t];
    if (t < 2)  s->wk[t] = wk[i*2+t];
  } else {
    for (int k = t; k < 512; k += kTPB) {
      int d = k >> 5, c = k & 31;
      g_a0s.Wq[k] = Wqkv[d*96 + c];
    }
    if (t < 16) { g_a0s.ln1g[t] = ln1g[t]; g_a0s.ln1b[t] = ln1b[t]; }
    if (t < 4)  g_a0s.wq[t] = wq[t];
    for (int k = t; k < kBot*16; k += kTPB) g_gls.Wemb[k] = Wemb[k];
    if (t < 16) { g_gls.bemb[t] = bemb[t]; g_gls.Wout[t] = Wout[t]; }
    if (t == 0) g_gls.bout[0] = bout[0];
  }
}

// ---------------- fused embed + stage-A(layer 0) ----------------
__global__ void __launch_bounds__(kTPB, 4) fusedEmbedA_kernel(const float* __restrict__ corr) {
  __shared__ float4 sT[10 * 257];
  int b = blockIdx.x / kBPB;
  int blk = blockIdx.x % kBPB;
  int t = threadIdx.x;
  int n = blk * kTPB + t;
  bool active = n < kN;
  float x[16];
  if (active) {
    u64 acc[8];
#pragma unroll
    for (int m = 0; m < 4; m++) ldc4(&cG.bemb[4*m], acc[2*m], acc[2*m+1]);
    const float* cp = corr + (size_t)b * kBot * kN + n;
#pragma unroll 13
    for (int c = 0; c < kBot; c++) {
      float v = fmaxf(cp[(size_t)c * kN], 0.f);
      u64 v2 = pack2(v, v);
#pragma unroll
      for (int m = 0; m < 4; m++) {
        u64 w0, w1; ldc4(&cG.Wemb[c*16 + 4*m], w0, w1);
        acc[2*m]   = fma2(w0, v2, acc[2*m]);
        acc[2*m+1] = fma2(w1, v2, acc[2*m+1]);
      }
    }
#pragma unroll
    for (int m = 0; m < 8; m++) unpack2(acc[m], x[2*m], x[2*m+1]);
  } else {
#pragma unroll
    for (int d = 0; d < 16; d++) x[d] = 0.f;
  }
  float4* xb = xblock(b, blk);
#pragma unroll
  for (int m = 0; m < 4; m++)
    xb[m * kTPB + t] = make_float4(x[4*m], x[4*m+1], x[4*m+2], x[4*m+3]);
  qstats_reduce(sT, x, active, n, cA.ln1g, cA.ln1b, cA.Wq, cA.wq,
                g_partQ + (size_t)blockIdx.x * 40);
}

// ---------------- stage B: overlapped finalize-Q + k stats ----------------
__global__ void __launch_bounds__(kTPB, 5) stageB_kernel() {
  __shared__ float4 sT[10 * 257];
  __shared__ float sgq[32];
  int b = blockIdx.x / kBPB;
  int blk = blockIdx.x % kBPB;
  int t = threadIdx.x;
  // phase A: issue finalize loads (results consumed after overlap window)
  float facc = finalize_acc(g_partQ, b);
  int n = blk * kTPB + t;
  bool active = n < kN;
  float x[16];
  const float4* xb = xblock(b, blk);
#pragma unroll
  for (int m = 0; m < 4; m++) {
    float4 t4 = xb[m * kTPB + t];
    x[4*m] = t4.x; x[4*m+1] = t4.y; x[4*m+2] = t4.z; x[4*m+3] = t4.w;
  }
  float y[16];
  ln16(x, cP.ln1g, cP.ln1b, y);
  float4 rt = g_rot[n];
  // GEMM for head-quad 0 (no sgq needed) — overlaps finalize load latency
  u64 a[8];
#pragma unroll
  for (int m = 0; m < 8; m++) a[m] = 0ull;
#pragma unroll
  for (int d = 0; d < 16; d++) {
    u64 yd = pack2(y[d], y[d]);
    const float* row = &cP.Wqkv[d*96 + 32];
#pragma unroll
    for (int h2 = 0; h2 < 4; h2++) {
      u64 w0, w1; ldc4(row + 4*h2, w0, w1);
      a[2*h2]   = fma2(w0, yd, a[2*h2]);
      a[2*h2+1] = fma2(w1, yd, a[2*h2+1]);
    }
  }
  // phase B: commit finalize, get sgq
  finalize_commit(facc, sgq);
#pragma unroll
  for (int hp = 0; hp < 2; hp++) {
    if (hp == 1) {
#pragma unroll
      for (int m = 0; m < 8; m++) a[m] = 0ull;
#pragma unroll
      for (int d = 0; d < 16; d++) {
        u64 yd = pack2(y[d], y[d]);
        const float* row = &cP.Wqkv[d*96 + 32 + 16];
#pragma unroll
        for (int h2 = 0; h2 < 4; h2++) {
          u64 w0, w1; ldc4(row + 4*h2, w0, w1);
          a[2*h2]   = fma2(w0, yd, a[2*h2]);
          a[2*h2+1] = fma2(w1, yd, a[2*h2+1]);
        }
      }
    }
    float v20[20];
#pragma unroll
    for (int h2 = 0; h2 < 4; h2++) {
      int h = hp * 4 + h2;
      float k0, k1, k2v, k3;
      unpack2(a[2*h2], k0, k1); unpack2(a[2*h2+1], k2v, k3);
      float p0 = k0*sgq[4*h+0] + k1*sgq[4*h+1];
      float p1 = k2v*sgq[4*h+2] + k3*sgq[4*h+3];
      float lgt = (p0*cP.wk[0] + p1*cP.wk[1]) * kScale;
      float e = active ? __expf(lgt) : 0.f;
      v20[h2*5+0] = e;
      v20[h2*5+1] = e * (k0*rt.x - k1*rt.y);
      v20[h2*5+2] = e * (k1*rt.x + k0*rt.y);
      v20[h2*5+3] = e * (k2v*rt.z - k3*rt.w);
      v20[h2*5+4] = e * (k3*rt.z + k2v*rt.w);
    }
    red_store(sT, v20, hp);
  }
  red_finish(sT, g_partK + (size_t)blockIdx.x * 40);
}

// ---------------- fused: overlapped finalize-K + stage C + stage-A(next) ----------------
__global__ void __launch_bounds__(kTPB, 4) fusedCA_kernel(float* __restrict__ out,
                                                          int last, int do_stats) {
  __shared__ float4 sT[10 * 257];
  __shared__ float sgk[32];
  int b = blockIdx.x / kBPB;
  int blk = blockIdx.x % kBPB;
  int t = threadIdx.x;
  // phase A: issue finalize loads
  float facc = finalize_acc(g_partK, b);
  int n = blk * kTPB + t;
  bool active = n < kN;
  float4* xb = xblock(b, blk);
  float x[16];
#pragma unroll
  for (int m = 0; m < 4; m++) {
    float4 t4 = xb[m * kTPB + t];
    x[4*m] = t4.x; x[4*m+1] = t4.y; x[4*m+2] = t4.z; x[4*m+3] = t4.w;
  }
  float y[16];
  ln16(x, cP.ln1g, cP.ln1b, y);

  // ao = boP + y@WqWo  (sgk-independent; overlaps finalize loads)
  u64 ao[8];
#pragma unroll
  for (int m = 0; m < 4; m++) ldc4(&cP.boP[4*m], ao[2*m], ao[2*m+1]);
#pragma unroll
  for (int d = 0; d < 16; d++) {
    u64 yd = pack2(y[d], y[d]);
    const float* row = &cP.WqWo[d*16];
#pragma unroll
    for (int m = 0; m < 4; m++) {
      u64 w0, w1; ldc4(row + 4*m, w0, w1);
      ao[2*m]   = fma2(w0, yd, ao[2*m]);
      ao[2*m+1] = fma2(w1, yd, ao[2*m+1]);
    }
  }
  // phase B: commit finalize, get sgk
  finalize_commit(facc, sgk);

  // v-GEMM in 2 head-quad passes; fold u into WrWo immediately
#pragma unroll
  for (int hp = 0; hp < 2; hp++) {
    u64 av[8];
#pragma unroll
    for (int m = 0; m < 8; m++) av[m] = 0ull;
#pragma unroll
    for (int d = 0; d < 16; d++) {
      u64 yd = pack2(y[d], y[d]);
      const float* row = &cP.Wqkv[d*96 + 64 + hp*16];
#pragma unroll
      for (int h2 = 0; h2 < 4; h2++) {
        u64 w0, w1; ldc4(row + 4*h2, w0, w1);
        av[2*h2]   = fma2(w0, yd, av[2*h2]);
        av[2*h2+1] = fma2(w1, yd, av[2*h2+1]);
      }
    }
#pragma unroll
    for (int h2 = 0; h2 < 4; h2++) {
      int h = hp * 4 + h2;
      float v0, v1, v2, v3;
      unpack2(av[2*h2], v0, v1); unpack2(av[2*h2+1], v2, v3);
      float u0 = v0*sgk[4*h+0] + v1*sgk[4*h+1];
      float u1 = v2*sgk[4*h+2] + v3*sgk[4*h+3];
#pragma unroll
      for (int p = 0; p < 2; p++) {
        float uv = p ? u1 : u0;
        u64 uc = pack2(uv, uv);
        const float* row = &cP.WrWo[(h*2 + p)*16];
#pragma unroll
        for (int m = 0; m < 4; m++) {
          u64 w0, w1; ldc4(row + 4*m, w0, w1);
          ao[2*m]   = fma2(w0, uc, ao[2*m]);
          ao[2*m+1] = fma2(w1, uc, ao[2*m+1]);
        }
      }
    }
  }
#pragma unroll
  for (int m = 0; m < 8; m++) {
    float a0, a1; unpack2(ao[m], a0, a1);
    x[2*m] += a0; x[2*m+1] += a1;
  }

  // FF block, 4 chunks of 16 hidden units (low register pressure)
  float y2[16];
  ln16(x, cP.ln2g, cP.ln2b, y2);
  u64 a2[8];
#pragma unroll
  for (int m = 0; m < 4; m++) ldc4(&cP.B2[4*m], a2[2*m], a2[2*m+1]);
#pragma unroll
  for (int jc = 0; jc < 4; jc++) {
    u64 hh[8];
#pragma unroll
    for (int m = 0; m < 4; m++) ldc4(&cP.B1[jc*16 + 4*m], hh[2*m], hh[2*m+1]);
#pragma unroll
    for (int d = 0; d < 16; d++) {
      u64 yd = pack2(y2[d], y2[d]);
      const float* row = &cP.W1[d*64 + jc*16];
#pragma unroll
      for (int m = 0; m < 4; m++) {
        u64 w0, w1; ldc4(row + 4*m, w0, w1);
        hh[2*m]   = fma2(w0, yd, hh[2*m]);
        hh[2*m+1] = fma2(w1, yd, hh[2*m+1]);
      }
    }
#pragma unroll
    for (int m = 0; m < 8; m++) {
      float p0, p1; unpack2(hh[m], p0, p1);
      float g0 = gelu_fast(p0);
      float g1 = gelu_fast(p1);
      int j0 = jc*16 + 2*m;
      u64 h0 = pack2(g0, g0);
      const float* w2r = &cP.W2[j0*16];
#pragma unroll
      for (int mm = 0; mm < 4; mm++) {
        u64 w0, w1; ldc4(w2r + 4*mm, w0, w1);
        a2[2*mm]   = fma2(w0, h0, a2[2*mm]);
        a2[2*mm+1] = fma2(w1, h0, a2[2*mm+1]);
      }
      u64 h1 = pack2(g1, g1);
      w2r += 16;
#pragma unroll
      for (int mm = 0; mm < 4; mm++) {
        u64 w0, w1; ldc4(w2r + 4*mm, w0, w1);
        a2[2*mm]   = fma2(w0, h1, a2[2*mm]);
        a2[2*mm+1] = fma2(w1, h1, a2[2*mm+1]);
      }
    }
  }
#pragma unroll
  for (int m = 0; m < 8; m++) {
    float a0, a1; unpack2(a2[m], a0, a1);
    x[2*m] += a0; x[2*m+1] += a1;
  }

  if (last) {
    if (active) {
      float o = cG.bout[0];
#pragma unroll
      for (int d = 0; d < 16; d++) o = fmaf(x[d], cG.Wout[d], o);
      out[(size_t)b * kN + n] = o;
    }
  } else {
#pragma unroll
    for (int m = 0; m < 4; m++)
      xb[m * kTPB + t] = make_float4(x[4*m], x[4*m+1], x[4*m+2], x[4*m+3]);
  }
  if (do_stats) {
    qstats_reduce(sT, x, active, n, cP.nLn1g, cP.nLn1b, cP.nWq, cP.nWqlog,
                  g_partQ + (size_t)blockIdx.x * 40);
  }
}

// ---------------- host launcher ----------------
extern "C" void kernel_launch(void* const* d_in, const int* in_sizes, int n_in,
                              void* d_out, int out_size) {
  (void)in_sizes; (void)n_in; (void)out_size;
  const float* corr  = (const float*)d_in[0];
  const float* W_emb = (const float*)d_in[1];
  const float* b_emb = (const float*)d_in[2];
  const float* ln1_g = (const float*)d_in[3];
  const float* ln1_b = (const float*)d_in[4];
  const float* W_qkv = (const float*)d_in[5];
  const float* w_qlog= (const float*)d_in[6];
  const float* w_klog= (const float*)d_in[7];
  const float* W_r   = (const float*)d_in[8];
  const float* b_r   = (const float*)d_in[9];
  const float* W_o   = (const float*)d_in[10];
  const float* b_o   = (const float*)d_in[11];
  const float* ln2_g = (const float*)d_in[12];
  const float* ln2_b = (const float*)d_in[13];
  const float* W_ff1 = (const float*)d_in[14];
  const float* b_ff1 = (const float*)d_in[15];
  const float* W_ff2 = (const float*)d_in[16];
  const float* b_ff2 = (const float*)d_in[17];
  const float* W_out = (const float*)d_in[18];
  const float* b_out = (const float*)d_in[19];
  float* out = (float*)d_out;

  rotprep_kernel<<<kBPB, kTPB>>>();
  gather_kernel<<<kL + 1, kTPB>>>(W_qkv, ln1_g, ln1_b, w_qlog, w_klog, W_r,
                                  b_r, W_o, b_o, ln2_g, ln2_b, W_ff1, b_ff1,
                                  W_ff2, b_ff2, W_emb, b_emb, W_out, b_out);

  void *pBanks = nullptr, *pA0 = nullptr, *pGl = nullptr;
  cudaGetSymbolAddress(&pBanks, g_banks);
  cudaGetSymbolAddress(&pA0, g_a0s);
  cudaGetSymbolAddress(&pGl, g_gls);

  cudaMemcpyToSymbolAsync(cG, pGl, sizeof(CGlob), 0, cudaMemcpyDeviceToDevice, 0);
  cudaMemcpyToSymbolAsync(cA, pA0, sizeof(CA0), 0, cudaMemcpyDeviceToDevice, 0);
  cudaMemcpyToSymbolAsync(cP, pBanks, sizeof(CParams), 0,
                          cudaMemcpyDeviceToDevice, 0);

  fusedEmbedA_kernel<<<kGrid, kTPB>>>(corr);

  for (int i = 0; i < kL; i++) {
    stageB_kernel<<<kGrid, kTPB>>>();
    fusedCA_kernel<<<kGrid, kTPB>>>(out, (i == kL - 1) ? 1 : 0,
                                    (i < kL - 1) ? 1 : 0);
    if (i + 1 < kL) {
      cudaMemcpyToSymbolAsync(
          cP, (const char*)pBanks + (size_t)(i + 1) * sizeof(CParams),
          sizeof(CParams), 0, cudaMemcpyDeviceToDevice, 0);
    }
  }
}